// round 1
// baseline (speedup 1.0000x reference)
#include <cuda_runtime.h>
#include <math.h>

#define BB   4
#define NSEQ 2048
#define EMB  1024
#define NH   16
#define HD   64
#define NTOK (BB * NSEQ)      // 8192
#define QKVN (3 * EMB)        // 3072

// Scratch (allocation-free: __device__ globals)
__device__ float g_q[BB * NH * NSEQ * HD];     // [b,h,n,d], pre-scaled by 1/8
__device__ float g_k[BB * NH * NSEQ * HD];
__device__ float g_v[BB * NH * NSEQ * HD];
__device__ float g_att[NTOK * EMB];            // [b,n, h*64+d]

// ---------------------------------------------------------------------------
// SGEMM (NT): C[m,n] = sum_k A[m,k] * W[n,k]  (+bias epilogue)
// MODE 0: A = x,  N = 3072, epilogue scatters into g_q/g_k/g_v (q *= 0.125)
// MODE 1: A = g_att, N = 1024, epilogue writes Cout (= d_out)
// Block tile 128x128, K-step 8, 256 threads, 8x8 per thread.
// ---------------------------------------------------------------------------
template <int MODE>
__global__ void __launch_bounds__(256) sgemm_nt(
    const float* __restrict__ A_ext,
    const float* __restrict__ W,
    const float* __restrict__ bias,
    float* __restrict__ Cout)
{
    const int K = EMB;
    const float* A = (MODE == 0) ? A_ext : g_att;

    __shared__ float As[8][128];
    __shared__ float Bs[8][128];

    const int tid  = threadIdx.x;
    const int tx   = tid & 15;
    const int ty   = tid >> 4;
    const int m0   = blockIdx.y * 128;
    const int n0   = blockIdx.x * 128;
    const int lrow = tid >> 1;
    const int lcol = (tid & 1) * 4;

    float acc[8][8];
#pragma unroll
    for (int i = 0; i < 8; i++)
#pragma unroll
        for (int j = 0; j < 8; j++) acc[i][j] = 0.f;

    for (int k0 = 0; k0 < K; k0 += 8) {
        float4 av = *(const float4*)&A[(size_t)(m0 + lrow) * K + k0 + lcol];
        float4 wv = *(const float4*)&W[(size_t)(n0 + lrow) * K + k0 + lcol];
        As[lcol + 0][lrow] = av.x;
        As[lcol + 1][lrow] = av.y;
        As[lcol + 2][lrow] = av.z;
        As[lcol + 3][lrow] = av.w;
        Bs[lcol + 0][lrow] = wv.x;
        Bs[lcol + 1][lrow] = wv.y;
        Bs[lcol + 2][lrow] = wv.z;
        Bs[lcol + 3][lrow] = wv.w;
        __syncthreads();

#pragma unroll
        for (int kk = 0; kk < 8; kk++) {
            float a[8], b[8];
            float4 t;
            t = *(const float4*)&As[kk][ty * 8 + 0]; a[0] = t.x; a[1] = t.y; a[2] = t.z; a[3] = t.w;
            t = *(const float4*)&As[kk][ty * 8 + 4]; a[4] = t.x; a[5] = t.y; a[6] = t.z; a[7] = t.w;
            t = *(const float4*)&Bs[kk][tx * 8 + 0]; b[0] = t.x; b[1] = t.y; b[2] = t.z; b[3] = t.w;
            t = *(const float4*)&Bs[kk][tx * 8 + 4]; b[4] = t.x; b[5] = t.y; b[6] = t.z; b[7] = t.w;
#pragma unroll
            for (int i = 0; i < 8; i++)
#pragma unroll
                for (int j = 0; j < 8; j++)
                    acc[i][j] = fmaf(a[i], b[j], acc[i][j]);
        }
        __syncthreads();
    }

    if (MODE == 0) {
        // n packed as (h, d, which): n = h*192 + d*3 + which
#pragma unroll
        for (int i = 0; i < 8; i++) {
            int m  = m0 + ty * 8 + i;
            int bb = m >> 11;            // /2048
            int nn = m & (NSEQ - 1);
#pragma unroll
            for (int j = 0; j < 8; j++) {
                int n      = n0 + tx * 8 + j;
                float val  = acc[i][j] + bias[n];
                int h      = n / 192;
                int rem    = n - h * 192;
                int d      = rem / 3;
                int which  = rem - d * 3;
                size_t idx = ((size_t)(bb * NH + h) * NSEQ + nn) * HD + d;
                if (which == 0)      g_q[idx] = val * 0.125f;   // 1/sqrt(64)
                else if (which == 1) g_k[idx] = val;
                else                 g_v[idx] = val;
            }
        }
    } else {
#pragma unroll
        for (int i = 0; i < 8; i++) {
            int m = m0 + ty * 8 + i;
#pragma unroll
            for (int j4 = 0; j4 < 8; j4 += 4) {
                int n = n0 + tx * 8 + j4;
                float4 o;
                o.x = acc[i][j4 + 0] + bias[n + 0];
                o.y = acc[i][j4 + 1] + bias[n + 1];
                o.z = acc[i][j4 + 2] + bias[n + 2];
                o.w = acc[i][j4 + 3] + bias[n + 3];
                *(float4*)&Cout[(size_t)m * EMB + n] = o;
            }
        }
    }
}

// ---------------------------------------------------------------------------
// Flash-attention (fp32, online softmax). One block = 64 queries of one (b,h).
// smem: Qs[64][68], KVs[64][68] (K then reused for V), Ss[64][68], m/l/alpha.
// 256 threads; 4x4 microtile per thread (ty -> 4 query rows, tx -> 4 cols).
// ---------------------------------------------------------------------------
#define TPAD 68
#define ATTN_SMEM ((3 * 64 * TPAD + 3 * 64) * sizeof(float))

__global__ void __launch_bounds__(256) attn_kernel()
{
    extern __shared__ float sm[];
    float* Qs   = sm;
    float* KVs  = sm + 64 * TPAD;
    float* Ss   = sm + 2 * 64 * TPAD;
    float* mrow = sm + 3 * 64 * TPAD;
    float* lrow = mrow + 64;
    float* arow = lrow + 64;

    const int tid = threadIdx.x;
    const int tx  = tid & 15;
    const int ty  = tid >> 4;
    const int bh  = blockIdx.y;
    const int b   = bh / NH;
    const int h   = bh - b * NH;
    const int q0  = blockIdx.x * 64;

    const float* Qg = g_q + (size_t)bh * NSEQ * HD;
    const float* Kg = g_k + (size_t)bh * NSEQ * HD;
    const float* Vg = g_v + (size_t)bh * NSEQ * HD;

    // Load Q tile (already scaled by 1/8)
    for (int i = tid; i < 64 * 16; i += 256) {
        int r = i >> 4, c = (i & 15) * 4;
        *(float4*)&Qs[r * TPAD + c] = *(const float4*)&Qg[(size_t)(q0 + r) * HD + c];
    }
    if (tid < 64) { mrow[tid] = -1e30f; lrow[tid] = 0.f; }

    float acc[4][4];
#pragma unroll
    for (int i = 0; i < 4; i++)
#pragma unroll
        for (int j = 0; j < 4; j++) acc[i][j] = 0.f;

    __syncthreads();

    for (int t0 = 0; t0 < NSEQ; t0 += 64) {
        // ---- load K tile ----
        for (int i = tid; i < 64 * 16; i += 256) {
            int r = i >> 4, c = (i & 15) * 4;
            *(float4*)&KVs[r * TPAD + c] = *(const float4*)&Kg[(size_t)(t0 + r) * HD + c];
        }
        __syncthreads();

        // ---- S = Q K^T (4x4 microtile) ----
        float s[4][4];
#pragma unroll
        for (int i = 0; i < 4; i++)
#pragma unroll
            for (int j = 0; j < 4; j++) s[i][j] = 0.f;

#pragma unroll
        for (int d4 = 0; d4 < 16; d4++) {
            float qr[4][4], kr[4][4];
#pragma unroll
            for (int i = 0; i < 4; i++) {
                float4 t = *(const float4*)&Qs[(ty * 4 + i) * TPAD + d4 * 4];
                qr[i][0] = t.x; qr[i][1] = t.y; qr[i][2] = t.z; qr[i][3] = t.w;
            }
#pragma unroll
            for (int j = 0; j < 4; j++) {
                float4 t = *(const float4*)&KVs[(tx * 4 + j) * TPAD + d4 * 4];
                kr[j][0] = t.x; kr[j][1] = t.y; kr[j][2] = t.z; kr[j][3] = t.w;
            }
#pragma unroll
            for (int i = 0; i < 4; i++)
#pragma unroll
                for (int j = 0; j < 4; j++)
#pragma unroll
                    for (int c = 0; c < 4; c++)
                        s[i][j] = fmaf(qr[i][c], kr[j][c], s[i][j]);
        }
#pragma unroll
        for (int i = 0; i < 4; i++)
#pragma unroll
            for (int j = 0; j < 4; j++)
                Ss[(ty * 4 + i) * TPAD + tx * 4 + j] = s[i][j];
        __syncthreads();

        // ---- online softmax (1 thread per row) ----
        if (tid < 64) {
            float m_old = mrow[tid];
            float mx    = m_old;
#pragma unroll 8
            for (int j = 0; j < 64; j++) mx = fmaxf(mx, Ss[tid * TPAD + j]);
            float alpha = __expf(m_old - mx);
            float sum   = 0.f;
#pragma unroll 8
            for (int j = 0; j < 64; j++) {
                float p = __expf(Ss[tid * TPAD + j] - mx);
                Ss[tid * TPAD + j] = p;
                sum += p;
            }
            mrow[tid] = mx;
            arow[tid] = alpha;
            lrow[tid] = lrow[tid] * alpha + sum;
        }
        // ---- load V tile into KVs (K reads are done) ----
        for (int i = tid; i < 64 * 16; i += 256) {
            int r = i >> 4, c = (i & 15) * 4;
            *(float4*)&KVs[r * TPAD + c] = *(const float4*)&Vg[(size_t)(t0 + r) * HD + c];
        }
        __syncthreads();

        // ---- O = O*alpha + P V ----
        float al[4];
#pragma unroll
        for (int i = 0; i < 4; i++) al[i] = arow[ty * 4 + i];
#pragma unroll
        for (int i = 0; i < 4; i++)
#pragma unroll
            for (int j = 0; j < 4; j++) acc[i][j] *= al[i];

#pragma unroll
        for (int k4 = 0; k4 < 16; k4++) {
            float pr[4][4], vr[4][4];
#pragma unroll
            for (int i = 0; i < 4; i++) {
                float4 t = *(const float4*)&Ss[(ty * 4 + i) * TPAD + k4 * 4];
                pr[i][0] = t.x; pr[i][1] = t.y; pr[i][2] = t.z; pr[i][3] = t.w;
            }
#pragma unroll
            for (int r = 0; r < 4; r++) {
                float4 t = *(const float4*)&KVs[(k4 * 4 + r) * TPAD + tx * 4];
                vr[r][0] = t.x; vr[r][1] = t.y; vr[r][2] = t.z; vr[r][3] = t.w;
            }
#pragma unroll
            for (int i = 0; i < 4; i++)
#pragma unroll
                for (int j = 0; j < 4; j++)
#pragma unroll
                    for (int r = 0; r < 4; r++)
                        acc[i][j] = fmaf(pr[i][r], vr[r][j], acc[i][j]);
        }
        __syncthreads();
    }

    // ---- epilogue: g_att[b, n, h*64+d] = acc / l ----
#pragma unroll
    for (int i = 0; i < 4; i++) {
        int r = ty * 4 + i;
        float inv = 1.0f / lrow[r];
        float4 o;
        o.x = acc[i][0] * inv;
        o.y = acc[i][1] * inv;
        o.z = acc[i][2] * inv;
        o.w = acc[i][3] * inv;
        size_t row = (size_t)b * NSEQ + (q0 + r);
        *(float4*)&g_att[row * EMB + h * HD + tx * 4] = o;
    }
}

// ---------------------------------------------------------------------------
extern "C" void kernel_launch(void* const* d_in, const int* in_sizes, int n_in,
                              void* d_out, int out_size)
{
    const float* x      = (const float*)d_in[0];
    const float* w_qkv  = (const float*)d_in[1];
    const float* b_qkv  = (const float*)d_in[2];
    const float* w_proj = (const float*)d_in[3];
    const float* b_proj = (const float*)d_in[4];
    float* out = (float*)d_out;

    cudaFuncSetAttribute(attn_kernel, cudaFuncAttributeMaxDynamicSharedMemorySize,
                         (int)ATTN_SMEM);

    // 1) QKV projection + de-interleave scatter
    sgemm_nt<0><<<dim3(QKVN / 128, NTOK / 128), 256>>>(x, w_qkv, b_qkv, nullptr);
    // 2) attention
    attn_kernel<<<dim3(NSEQ / 64, BB * NH), 256, ATTN_SMEM>>>();
    // 3) output projection
    sgemm_nt<1><<<dim3(EMB / 128, NTOK / 128), 256>>>(nullptr, w_proj, b_proj, out);
}

// round 2
// speedup vs baseline: 2.2428x; 2.2428x over previous
#include <cuda_runtime.h>
#include <cuda_bf16.h>
#include <math.h>
#include <stdint.h>

#define BB   4
#define NSEQ 2048
#define EMB  1024
#define NH   16
#define HD   64
#define NTOK (BB * NSEQ)      // 8192
#define QKVN (3 * EMB)        // 3072

typedef __nv_bfloat16 bf16;

// ---------------- scratch (__device__ globals; allocation-free) -------------
__device__ bf16 g_xh[NTOK * EMB],  g_xl[NTOK * EMB];
__device__ bf16 g_wqh[QKVN * EMB], g_wql[QKVN * EMB];
__device__ bf16 g_wph[EMB * EMB],  g_wpl[EMB * EMB];
__device__ bf16 g_qh[BB*NH*NSEQ*HD], g_ql[BB*NH*NSEQ*HD];
__device__ bf16 g_kh[BB*NH*NSEQ*HD], g_kl[BB*NH*NSEQ*HD];
__device__ bf16 g_vh[BB*NH*NSEQ*HD], g_vl[BB*NH*NSEQ*HD];
__device__ bf16 g_atth[NTOK * EMB], g_attl[NTOK * EMB];

// ---------------- helpers ----------------------------------------------------
__device__ __forceinline__ uint32_t smaddr(const void* p) {
    return (uint32_t)__cvta_generic_to_shared(p);
}
__device__ __forceinline__ void ldsm_x4(uint32_t& r0, uint32_t& r1, uint32_t& r2,
                                        uint32_t& r3, uint32_t a) {
    asm volatile("ldmatrix.sync.aligned.m8n8.x4.shared.b16 {%0,%1,%2,%3},[%4];\n"
                 : "=r"(r0), "=r"(r1), "=r"(r2), "=r"(r3) : "r"(a));
}
__device__ __forceinline__ void ldsm_x4t(uint32_t& r0, uint32_t& r1, uint32_t& r2,
                                         uint32_t& r3, uint32_t a) {
    asm volatile("ldmatrix.sync.aligned.m8n8.x4.trans.shared.b16 {%0,%1,%2,%3},[%4];\n"
                 : "=r"(r0), "=r"(r1), "=r"(r2), "=r"(r3) : "r"(a));
}
__device__ __forceinline__ void mma_bf16(float c[4], const uint32_t a[4],
                                         const uint32_t b[2]) {
    asm volatile(
        "mma.sync.aligned.m16n8k16.row.col.f32.bf16.bf16.f32 "
        "{%0,%1,%2,%3}, {%4,%5,%6,%7}, {%8,%9}, {%0,%1,%2,%3};\n"
        : "+f"(c[0]), "+f"(c[1]), "+f"(c[2]), "+f"(c[3])
        : "r"(a[0]), "r"(a[1]), "r"(a[2]), "r"(a[3]), "r"(b[0]), "r"(b[1]));
}
__device__ __forceinline__ void bsplit(float v, bf16& h, bf16& l) {
    h = __float2bfloat16(v);
    l = __float2bfloat16(v - __bfloat162float(h));
}
// FMA-pipe exp (no MUFU). Valid for x <= 0 (clamped below).
__device__ __forceinline__ float fast_exp(float x) {
    x = fmaxf(x, -86.0f);
    float y = x * 1.4426950408889634f;
    float r = rintf(y);
    float f = y - r;
    float p = 0.00133819f;
    p = fmaf(p, f, 0.00961804f);
    p = fmaf(p, f, 0.05550411f);
    p = fmaf(p, f, 0.24022651f);
    p = fmaf(p, f, 0.69314718f);
    p = fmaf(p, f, 1.0f);
    int e = (int)r;
    return p * __int_as_float((e + 127) << 23);
}

// ---------------- split kernel (fp32 -> bf16 hi/lo) --------------------------
__global__ void __launch_bounds__(256) split_kernel(
    const float4* __restrict__ in, __nv_bfloat162* __restrict__ h,
    __nv_bfloat162* __restrict__ l, int n4)
{
    int i = blockIdx.x * 256 + threadIdx.x;
    if (i >= n4) return;
    float4 v = in[i];
    bf16 h0, l0, h1, l1, h2, l2, h3, l3;
    bsplit(v.x, h0, l0); bsplit(v.y, h1, l1);
    bsplit(v.z, h2, l2); bsplit(v.w, h3, l3);
    __nv_bfloat162 t;
    t.x = h0; t.y = h1; h[2 * i] = t;
    t.x = h2; t.y = h3; h[2 * i + 1] = t;
    t.x = l0; t.y = l1; l[2 * i] = t;
    t.x = l2; t.y = l3; l[2 * i + 1] = t;
}

// ---------------- GEMM (NT, bf16 3-pass split, mma.sync) ---------------------
// C[m,n] = sum_k A[m,k]*W[n,k]  (fp32 acc) + bias
// MODE 0: A=(xh,xl), W=(wqh,wql), epilogue scatters q/k/v split (q *= 0.125)
// MODE 1: A=(atth,attl), W=(wph,wpl), epilogue writes fp32 Cout
#define GEMM_SMEM (4 * 128 * 72 * 2)

template <int MODE>
__global__ void __launch_bounds__(256) gemm_bf16(
    const bf16* __restrict__ Ah_, const bf16* __restrict__ Al_,
    const bf16* __restrict__ Wh_, const bf16* __restrict__ Wl_,
    const float* __restrict__ bias, float* __restrict__ Cout)
{
    constexpr int K = EMB;
    extern __shared__ bf16 smg[];
    bf16* sAh = smg;
    bf16* sAl = sAh + 128 * 72;
    bf16* sWh = sAl + 128 * 72;
    bf16* sWl = sWh + 128 * 72;

    const int tid  = threadIdx.x;
    const int lane = tid & 31;
    const int warp = tid >> 5;
    const int m0 = blockIdx.y * 128;
    const int n0 = blockIdx.x * 128;
    const int wm = (warp >> 1) * 32;
    const int wn = (warp & 1) * 64;

    const int a_row = lane & 15;
    const int a_csel = (lane >> 4) * 8;
    const int b_nrow = (lane & 7) + (lane >> 4) * 8;
    const int b_kcol = ((lane >> 3) & 1) * 8;

    float acc[2][8][4];
#pragma unroll
    for (int i = 0; i < 2; i++)
#pragma unroll
        for (int j = 0; j < 8; j++)
#pragma unroll
            for (int e = 0; e < 4; e++) acc[i][j][e] = 0.f;

    for (int k0 = 0; k0 < K; k0 += 64) {
#pragma unroll
        for (int i = 0; i < 4; i++) {
            int s = tid + i * 256;
            int r = s >> 3;
            int c = (s & 7) * 8;
            *(uint4*)&sAh[r * 72 + c] = *(const uint4*)&Ah_[(size_t)(m0 + r) * K + k0 + c];
            *(uint4*)&sAl[r * 72 + c] = *(const uint4*)&Al_[(size_t)(m0 + r) * K + k0 + c];
            *(uint4*)&sWh[r * 72 + c] = *(const uint4*)&Wh_[(size_t)(n0 + r) * K + k0 + c];
            *(uint4*)&sWl[r * 72 + c] = *(const uint4*)&Wl_[(size_t)(n0 + r) * K + k0 + c];
        }
        __syncthreads();
#pragma unroll
        for (int kc = 0; kc < 4; kc++) {
            uint32_t ah[2][4], al[2][4];
#pragma unroll
            for (int i = 0; i < 2; i++) {
                uint32_t ad = smaddr(&sAh[(wm + i * 16 + a_row) * 72 + kc * 16 + a_csel]);
                ldsm_x4(ah[i][0], ah[i][1], ah[i][2], ah[i][3], ad);
                ad = smaddr(&sAl[(wm + i * 16 + a_row) * 72 + kc * 16 + a_csel]);
                ldsm_x4(al[i][0], al[i][1], al[i][2], al[i][3], ad);
            }
            uint32_t bh[8][2], bl[8][2];
#pragma unroll
            for (int jp = 0; jp < 4; jp++) {
                uint32_t ad = smaddr(&sWh[(wn + jp * 16 + b_nrow) * 72 + kc * 16 + b_kcol]);
                ldsm_x4(bh[2 * jp][0], bh[2 * jp][1], bh[2 * jp + 1][0], bh[2 * jp + 1][1], ad);
                ad = smaddr(&sWl[(wn + jp * 16 + b_nrow) * 72 + kc * 16 + b_kcol]);
                ldsm_x4(bl[2 * jp][0], bl[2 * jp][1], bl[2 * jp + 1][0], bl[2 * jp + 1][1], ad);
            }
#pragma unroll
            for (int i = 0; i < 2; i++)
#pragma unroll
                for (int j = 0; j < 8; j++) {
                    mma_bf16(acc[i][j], ah[i], bh[j]);
                    mma_bf16(acc[i][j], ah[i], bl[j]);
                    mma_bf16(acc[i][j], al[i], bh[j]);
                }
        }
        __syncthreads();
    }

    const int g = lane >> 2, t = lane & 3;
    if (MODE == 0) {
#pragma unroll
        for (int i = 0; i < 2; i++)
#pragma unroll
            for (int j = 0; j < 8; j++)
#pragma unroll
                for (int e = 0; e < 4; e++) {
                    int row = m0 + wm + i * 16 + g + (e >> 1) * 8;
                    int col = n0 + wn + j * 8 + 2 * t + (e & 1);
                    float val = acc[i][j][e] + bias[col];
                    int h = col / 192;
                    int rem = col - h * 192;
                    int d = rem / 3;
                    int which = rem - d * 3;
                    int bb = row >> 11;
                    int nn = row & (NSEQ - 1);
                    size_t idx = ((size_t)(bb * NH + h) * NSEQ + nn) * HD + d;
                    bf16 hi, lo;
                    if (which == 0) {
                        bsplit(val * 0.125f, hi, lo);
                        g_qh[idx] = hi; g_ql[idx] = lo;
                    } else if (which == 1) {
                        bsplit(val, hi, lo);
                        g_kh[idx] = hi; g_kl[idx] = lo;
                    } else {
                        bsplit(val, hi, lo);
                        g_vh[idx] = hi; g_vl[idx] = lo;
                    }
                }
    } else {
#pragma unroll
        for (int i = 0; i < 2; i++)
#pragma unroll
            for (int j = 0; j < 8; j++)
#pragma unroll
                for (int e = 0; e < 4; e++) {
                    int row = m0 + wm + i * 16 + g + (e >> 1) * 8;
                    int col = n0 + wn + j * 8 + 2 * t + (e & 1);
                    Cout[(size_t)row * EMB + col] = acc[i][j][e] + bias[col];
                }
    }
}

// ---------------- flash attention (bf16 split mma, smem softmax) -------------
// Block = 128 q-rows x one (b,h). KV tiles of 128. 8 warps x 16 rows each.
#define SOFF_Q   0
#define SOFF_QL  (128 * 72)
#define SOFF_KV  (2 * 128 * 72)
#define SOFF_KVL (3 * 128 * 72)
#define SOFF_SF  (4 * 128 * 72 * 2)                    // bytes
#define SOFF_PH  (SOFF_SF + 128 * 130 * 4)             // bytes
#define SOFF_PL  (SOFF_PH + 128 * 136 * 2)
#define SOFF_ST  (SOFF_PL + 128 * 136 * 2)
#define ATTN_SMEM (SOFF_ST + 3 * 128 * 4)

__global__ void __launch_bounds__(256) attn_bf16()
{
    extern __shared__ char smraw[];
    bf16*  Qh  = (bf16*)smraw;
    bf16*  Ql  = Qh + 128 * 72;
    bf16*  KVh = Ql + 128 * 72;
    bf16*  KVl = KVh + 128 * 72;
    float* Sf  = (float*)(smraw + SOFF_SF);
    bf16*  Ph  = (bf16*)(smraw + SOFF_PH);
    bf16*  Pl  = (bf16*)(smraw + SOFF_PL);
    float* mrow = (float*)(smraw + SOFF_ST);
    float* lrow = mrow + 128;
    float* arow = lrow + 128;

    const int tid  = threadIdx.x;
    const int lane = tid & 31;
    const int warp = tid >> 5;
    const int bh = blockIdx.y;
    const int b  = bh >> 4;
    const int h  = bh & 15;
    const int q0 = blockIdx.x * 128;

    const bf16* Qgh = g_qh + (size_t)bh * NSEQ * HD;
    const bf16* Qgl = g_ql + (size_t)bh * NSEQ * HD;
    const bf16* Kgh = g_kh + (size_t)bh * NSEQ * HD;
    const bf16* Kgl = g_kl + (size_t)bh * NSEQ * HD;
    const bf16* Vgh = g_vh + (size_t)bh * NSEQ * HD;
    const bf16* Vgl = g_vl + (size_t)bh * NSEQ * HD;

#pragma unroll
    for (int i = 0; i < 4; i++) {
        int s = tid + i * 256;
        int r = s >> 3;
        int c = (s & 7) * 8;
        *(uint4*)&Qh[r * 72 + c] = *(const uint4*)&Qgh[(size_t)(q0 + r) * HD + c];
        *(uint4*)&Ql[r * 72 + c] = *(const uint4*)&Qgl[(size_t)(q0 + r) * HD + c];
    }
    if (tid < 128) { mrow[tid] = -1e30f; lrow[tid] = 0.f; }

    float oacc[8][4];
#pragma unroll
    for (int j = 0; j < 8; j++)
#pragma unroll
        for (int e = 0; e < 4; e++) oacc[j][e] = 0.f;

    const int a_row = lane & 15;
    const int a_csel = (lane >> 4) * 8;
    const int b_nrow = (lane & 7) + (lane >> 4) * 8;
    const int b_kcol = ((lane >> 3) & 1) * 8;
    const int g = lane >> 2, t = lane & 3;

    __syncthreads();

    for (int t0 = 0; t0 < NSEQ; t0 += 128) {
        // ---- load K tile ----
#pragma unroll
        for (int i = 0; i < 4; i++) {
            int s = tid + i * 256;
            int r = s >> 3;
            int c = (s & 7) * 8;
            *(uint4*)&KVh[r * 72 + c] = *(const uint4*)&Kgh[(size_t)(t0 + r) * HD + c];
            *(uint4*)&KVl[r * 72 + c] = *(const uint4*)&Kgl[(size_t)(t0 + r) * HD + c];
        }
        __syncthreads();

        // ---- S = Q K^T ----
        float sacc[16][4];
#pragma unroll
        for (int j = 0; j < 16; j++)
#pragma unroll
            for (int e = 0; e < 4; e++) sacc[j][e] = 0.f;

#pragma unroll
        for (int kc = 0; kc < 4; kc++) {
            uint32_t ah[4], al[4];
            uint32_t ad = smaddr(&Qh[(16 * warp + a_row) * 72 + kc * 16 + a_csel]);
            ldsm_x4(ah[0], ah[1], ah[2], ah[3], ad);
            ad = smaddr(&Ql[(16 * warp + a_row) * 72 + kc * 16 + a_csel]);
            ldsm_x4(al[0], al[1], al[2], al[3], ad);
#pragma unroll
            for (int jp = 0; jp < 8; jp++) {
                uint32_t bhf[4], blf[4];
                ad = smaddr(&KVh[(jp * 16 + b_nrow) * 72 + kc * 16 + b_kcol]);
                ldsm_x4(bhf[0], bhf[1], bhf[2], bhf[3], ad);
                ad = smaddr(&KVl[(jp * 16 + b_nrow) * 72 + kc * 16 + b_kcol]);
                ldsm_x4(blf[0], blf[1], blf[2], blf[3], ad);
                mma_bf16(sacc[2 * jp],     ah, &bhf[0]);
                mma_bf16(sacc[2 * jp],     ah, &blf[0]);
                mma_bf16(sacc[2 * jp],     al, &bhf[0]);
                mma_bf16(sacc[2 * jp + 1], ah, &bhf[2]);
                mma_bf16(sacc[2 * jp + 1], ah, &blf[2]);
                mma_bf16(sacc[2 * jp + 1], al, &bhf[2]);
            }
        }
        // ---- store S tile ----
#pragma unroll
        for (int j = 0; j < 16; j++) {
            int row = 16 * warp + g;
            float2 v01; v01.x = sacc[j][0]; v01.y = sacc[j][1];
            float2 v23; v23.x = sacc[j][2]; v23.y = sacc[j][3];
            *(float2*)&Sf[row * 130 + j * 8 + 2 * t]       = v01;
            *(float2*)&Sf[(row + 8) * 130 + j * 8 + 2 * t] = v23;
        }
        __syncthreads();

        // ---- load V tile (overwrite K buffers; overlap with softmax) ----
#pragma unroll
        for (int i = 0; i < 4; i++) {
            int s = tid + i * 256;
            int r = s >> 3;
            int c = (s & 7) * 8;
            *(uint4*)&KVh[r * 72 + c] = *(const uint4*)&Vgh[(size_t)(t0 + r) * HD + c];
            *(uint4*)&KVl[r * 72 + c] = *(const uint4*)&Vgl[(size_t)(t0 + r) * HD + c];
        }

        // ---- online softmax; write P (split) ----
        {
            int row = tid >> 1;
            int cb = (tid & 1) * 64;
            const float* srow = &Sf[row * 130 + cb];
            float mx = -1e30f;
#pragma unroll 16
            for (int j = 0; j < 64; j++) mx = fmaxf(mx, srow[j]);
            mx = fmaxf(mx, __shfl_xor_sync(0xffffffff, mx, 1));
            float mold = mrow[row];
            float mnew = fmaxf(mold, mx);
            float sum = 0.f;
#pragma unroll 8
            for (int j = 0; j < 64; j++) {
                float p = fast_exp(srow[j] - mnew);
                sum += p;
                bf16 hi, lo;
                bsplit(p, hi, lo);
                Ph[row * 136 + cb + j] = hi;
                Pl[row * 136 + cb + j] = lo;
            }
            sum += __shfl_xor_sync(0xffffffff, sum, 1);
            if ((tid & 1) == 0) {
                float alpha = fast_exp(mold - mnew);
                mrow[row] = mnew;
                arow[row] = alpha;
                lrow[row] = lrow[row] * alpha + sum;
            }
        }
        __syncthreads();

        // ---- O = O*alpha + P V ----
        {
            float a0 = arow[16 * warp + g];
            float a1 = arow[16 * warp + g + 8];
#pragma unroll
            for (int j = 0; j < 8; j++) {
                oacc[j][0] *= a0; oacc[j][1] *= a0;
                oacc[j][2] *= a1; oacc[j][3] *= a1;
            }
        }
#pragma unroll
        for (int kc = 0; kc < 8; kc++) {
            uint32_t ah[4], al[4];
            uint32_t ad = smaddr(&Ph[(16 * warp + a_row) * 136 + kc * 16 + a_csel]);
            ldsm_x4(ah[0], ah[1], ah[2], ah[3], ad);
            ad = smaddr(&Pl[(16 * warp + a_row) * 136 + kc * 16 + a_csel]);
            ldsm_x4(al[0], al[1], al[2], al[3], ad);
#pragma unroll
            for (int jp = 0; jp < 4; jp++) {
                uint32_t bhf[4], blf[4];
                ad = smaddr(&KVh[(kc * 16 + a_row) * 72 + jp * 16 + a_csel]);
                ldsm_x4t(bhf[0], bhf[1], bhf[2], bhf[3], ad);
                ad = smaddr(&KVl[(kc * 16 + a_row) * 72 + jp * 16 + a_csel]);
                ldsm_x4t(blf[0], blf[1], blf[2], blf[3], ad);
                mma_bf16(oacc[2 * jp],     ah, &bhf[0]);
                mma_bf16(oacc[2 * jp],     ah, &blf[0]);
                mma_bf16(oacc[2 * jp],     al, &bhf[0]);
                mma_bf16(oacc[2 * jp + 1], ah, &bhf[2]);
                mma_bf16(oacc[2 * jp + 1], ah, &blf[2]);
                mma_bf16(oacc[2 * jp + 1], al, &bhf[2]);
            }
        }
        __syncthreads();
    }

    // ---- epilogue: split(O/l) -> g_atth/g_attl at [b, q, h*64+d] ----
    float inv0 = 1.0f / lrow[16 * warp + g];
    float inv1 = 1.0f / lrow[16 * warp + g + 8];
#pragma unroll
    for (int j = 0; j < 8; j++)
#pragma unroll
        for (int e = 0; e < 4; e++) {
            int row = 16 * warp + g + (e >> 1) * 8;
            int col = j * 8 + 2 * t + (e & 1);
            float val = oacc[j][e] * ((e >> 1) ? inv1 : inv0);
            size_t off = ((size_t)b * NSEQ + q0 + row) * EMB + h * HD + col;
            bf16 hi, lo;
            bsplit(val, hi, lo);
            g_atth[off] = hi;
            g_attl[off] = lo;
        }
}

// ---------------------------------------------------------------------------
extern "C" void kernel_launch(void* const* d_in, const int* in_sizes, int n_in,
                              void* d_out, int out_size)
{
    const float* x      = (const float*)d_in[0];
    const float* w_qkv  = (const float*)d_in[1];
    const float* b_qkv  = (const float*)d_in[2];
    const float* w_proj = (const float*)d_in[3];
    const float* b_proj = (const float*)d_in[4];
    float* out = (float*)d_out;

    static int inited = 0;
    if (!inited) {
        cudaFuncSetAttribute(gemm_bf16<0>, cudaFuncAttributeMaxDynamicSharedMemorySize, GEMM_SMEM);
        cudaFuncSetAttribute(gemm_bf16<1>, cudaFuncAttributeMaxDynamicSharedMemorySize, GEMM_SMEM);
        cudaFuncSetAttribute(attn_bf16, cudaFuncAttributeMaxDynamicSharedMemorySize, (int)ATTN_SMEM);
        inited = 1;
    }

    bf16 *xh, *xl, *wqh, *wql, *wph, *wpl, *atth, *attl;
    cudaGetSymbolAddress((void**)&xh,  g_xh);  cudaGetSymbolAddress((void**)&xl,  g_xl);
    cudaGetSymbolAddress((void**)&wqh, g_wqh); cudaGetSymbolAddress((void**)&wql, g_wql);
    cudaGetSymbolAddress((void**)&wph, g_wph); cudaGetSymbolAddress((void**)&wpl, g_wpl);
    cudaGetSymbolAddress((void**)&atth, g_atth); cudaGetSymbolAddress((void**)&attl, g_attl);

    // 1) split inputs to bf16 hi/lo
    split_kernel<<<(NTOK * EMB) / 1024, 256>>>((const float4*)x,
        (__nv_bfloat162*)xh, (__nv_bfloat162*)xl, NTOK * EMB / 4);
    split_kernel<<<(QKVN * EMB) / 1024, 256>>>((const float4*)w_qkv,
        (__nv_bfloat162*)wqh, (__nv_bfloat162*)wql, QKVN * EMB / 4);
    split_kernel<<<(EMB * EMB) / 1024, 256>>>((const float4*)w_proj,
        (__nv_bfloat162*)wph, (__nv_bfloat162*)wpl, EMB * EMB / 4);

    // 2) QKV projection + scatter (q pre-scaled by 1/8, all split to bf16 hi/lo)
    gemm_bf16<0><<<dim3(QKVN / 128, NTOK / 128), 256, GEMM_SMEM>>>(
        xh, xl, wqh, wql, b_qkv, nullptr);

    // 3) flash attention
    attn_bf16<<<dim3(NSEQ / 128, BB * NH), 256, ATTN_SMEM>>>();

    // 4) output projection
    gemm_bf16<1><<<dim3(EMB / 128, NTOK / 128), 256, GEMM_SMEM>>>(
        atth, attl, wph, wpl, b_proj, out);
}

// round 3
// speedup vs baseline: 3.1060x; 1.3849x over previous
#include <cuda_runtime.h>
#include <cuda_bf16.h>
#include <math.h>
#include <stdint.h>

#define BB   4
#define NSEQ 2048
#define EMB  1024
#define NH   16
#define HD   64
#define NTOK (BB * NSEQ)      // 8192
#define QKVN (3 * EMB)        // 3072

typedef __nv_bfloat16 bf16;

// ---------------- scratch (__device__ globals; allocation-free) -------------
__device__ bf16 g_xh[NTOK * EMB],  g_xl[NTOK * EMB];
__device__ bf16 g_wqh[QKVN * EMB], g_wql[QKVN * EMB];
__device__ bf16 g_wph[EMB * EMB],  g_wpl[EMB * EMB];
__device__ bf16 g_qh[BB*NH*NSEQ*HD], g_ql[BB*NH*NSEQ*HD];
__device__ bf16 g_kh[BB*NH*NSEQ*HD], g_kl[BB*NH*NSEQ*HD];
__device__ bf16 g_vh[BB*NH*NSEQ*HD], g_vl[BB*NH*NSEQ*HD];
__device__ bf16 g_atth[NTOK * EMB], g_attl[NTOK * EMB];

// ---------------- helpers ----------------------------------------------------
__device__ __forceinline__ uint32_t smaddr(const void* p) {
    return (uint32_t)__cvta_generic_to_shared(p);
}
__device__ __forceinline__ void ldsm_x4(uint32_t& r0, uint32_t& r1, uint32_t& r2,
                                        uint32_t& r3, uint32_t a) {
    asm volatile("ldmatrix.sync.aligned.m8n8.x4.shared.b16 {%0,%1,%2,%3},[%4];\n"
                 : "=r"(r0), "=r"(r1), "=r"(r2), "=r"(r3) : "r"(a));
}
__device__ __forceinline__ void ldsm_x4t(uint32_t& r0, uint32_t& r1, uint32_t& r2,
                                         uint32_t& r3, uint32_t a) {
    asm volatile("ldmatrix.sync.aligned.m8n8.x4.trans.shared.b16 {%0,%1,%2,%3},[%4];\n"
                 : "=r"(r0), "=r"(r1), "=r"(r2), "=r"(r3) : "r"(a));
}
__device__ __forceinline__ void mma_bf16(float c[4], const uint32_t a[4],
                                         const uint32_t b[2]) {
    asm volatile(
        "mma.sync.aligned.m16n8k16.row.col.f32.bf16.bf16.f32 "
        "{%0,%1,%2,%3}, {%4,%5,%6,%7}, {%8,%9}, {%0,%1,%2,%3};\n"
        : "+f"(c[0]), "+f"(c[1]), "+f"(c[2]), "+f"(c[3])
        : "r"(a[0]), "r"(a[1]), "r"(a[2]), "r"(a[3]), "r"(b[0]), "r"(b[1]));
}
__device__ __forceinline__ void bsplit(float v, bf16& h, bf16& l) {
    h = __float2bfloat16(v);
    l = __float2bfloat16(v - __bfloat162float(h));
}
__device__ __forceinline__ uint32_t pack2(bf16 a, bf16 b) {
    __nv_bfloat162 t; t.x = a; t.y = b;
    return *(uint32_t*)&t;
}
// FMA-pipe exp (no MUFU). Valid for x <= 0 (clamped below).
__device__ __forceinline__ float fast_exp(float x) {
    x = fmaxf(x, -86.0f);
    float y = x * 1.4426950408889634f;
    float r = rintf(y);
    float f = y - r;
    float p = 0.00133819f;
    p = fmaf(p, f, 0.00961804f);
    p = fmaf(p, f, 0.05550411f);
    p = fmaf(p, f, 0.24022651f);
    p = fmaf(p, f, 0.69314718f);
    p = fmaf(p, f, 1.0f);
    int e = (int)r;
    return p * __int_as_float((e + 127) << 23);
}
// cp.async 16B
__device__ __forceinline__ void cp16(void* dst, const void* src) {
    asm volatile("cp.async.cg.shared.global [%0],[%1],16;\n"
                 :: "r"(smaddr(dst)), "l"(src));
}
__device__ __forceinline__ void cpcommit() {
    asm volatile("cp.async.commit_group;\n");
}
template <int N>
__device__ __forceinline__ void cpwait() {
    asm volatile("cp.async.wait_group %0;\n" :: "n"(N));
}

// ---------------- split kernel (fp32 -> bf16 hi/lo) --------------------------
__global__ void __launch_bounds__(256) split_kernel(
    const float4* __restrict__ in, __nv_bfloat162* __restrict__ h,
    __nv_bfloat162* __restrict__ l, int n4)
{
    int i = blockIdx.x * 256 + threadIdx.x;
    if (i >= n4) return;
    float4 v = in[i];
    bf16 h0, l0, h1, l1, h2, l2, h3, l3;
    bsplit(v.x, h0, l0); bsplit(v.y, h1, l1);
    bsplit(v.z, h2, l2); bsplit(v.w, h3, l3);
    __nv_bfloat162 t;
    t.x = h0; t.y = h1; h[2 * i] = t;
    t.x = h2; t.y = h3; h[2 * i + 1] = t;
    t.x = l0; t.y = l1; l[2 * i] = t;
    t.x = l2; t.y = l3; l[2 * i + 1] = t;
}

// ---------------- GEMM (NT, bf16 3-pass split, mma.sync, 2-stage cp.async) ---
#define GEMM_STAGE (128 * 72)
#define GEMM_SMEM  (2 * 4 * GEMM_STAGE * 2)   // 147456 bytes

template <int MODE>
__global__ void __launch_bounds__(256) gemm_bf16(
    const bf16* __restrict__ Ah_, const bf16* __restrict__ Al_,
    const bf16* __restrict__ Wh_, const bf16* __restrict__ Wl_,
    const float* __restrict__ bias, float* __restrict__ Cout)
{
    constexpr int K = EMB;
    extern __shared__ bf16 smg[];

    const int tid  = threadIdx.x;
    const int lane = tid & 31;
    const int warp = tid >> 5;
    const int m0 = blockIdx.y * 128;
    const int n0 = blockIdx.x * 128;
    const int wm = (warp >> 1) * 32;
    const int wn = (warp & 1) * 64;

    const int a_row = lane & 15;
    const int a_csel = (lane >> 4) * 8;
    const int b_nrow = (lane & 7) + (lane >> 4) * 8;
    const int b_kcol = ((lane >> 3) & 1) * 8;

    float acc[2][8][4];
#pragma unroll
    for (int i = 0; i < 2; i++)
#pragma unroll
        for (int j = 0; j < 8; j++)
#pragma unroll
            for (int e = 0; e < 4; e++) acc[i][j][e] = 0.f;

    // stage st, array arr (0=Ah,1=Al,2=Wh,3=Wl)
    auto buf = [&](int st, int arr) -> bf16* { return smg + (st * 4 + arr) * GEMM_STAGE; };
    auto load_stage = [&](int st, int k0) {
#pragma unroll
        for (int i = 0; i < 4; i++) {
            int s = tid + i * 256;
            int r = s >> 3;
            int c = (s & 7) * 8;
            cp16(buf(st, 0) + r * 72 + c, Ah_ + (size_t)(m0 + r) * K + k0 + c);
            cp16(buf(st, 1) + r * 72 + c, Al_ + (size_t)(m0 + r) * K + k0 + c);
            cp16(buf(st, 2) + r * 72 + c, Wh_ + (size_t)(n0 + r) * K + k0 + c);
            cp16(buf(st, 3) + r * 72 + c, Wl_ + (size_t)(n0 + r) * K + k0 + c);
        }
    };

    load_stage(0, 0);
    cpcommit();

    for (int kt = 0; kt < K / 64; kt++) {
        int cb = kt & 1;
        if (kt + 1 < K / 64) {
            load_stage(cb ^ 1, (kt + 1) * 64);
            cpcommit();
            cpwait<1>();
        } else {
            cpwait<0>();
        }
        __syncthreads();

        bf16* sAh = buf(cb, 0);
        bf16* sAl = buf(cb, 1);
        bf16* sWh = buf(cb, 2);
        bf16* sWl = buf(cb, 3);
#pragma unroll
        for (int kc = 0; kc < 4; kc++) {
            uint32_t ah[2][4], al[2][4];
#pragma unroll
            for (int i = 0; i < 2; i++) {
                uint32_t ad = smaddr(&sAh[(wm + i * 16 + a_row) * 72 + kc * 16 + a_csel]);
                ldsm_x4(ah[i][0], ah[i][1], ah[i][2], ah[i][3], ad);
                ad = smaddr(&sAl[(wm + i * 16 + a_row) * 72 + kc * 16 + a_csel]);
                ldsm_x4(al[i][0], al[i][1], al[i][2], al[i][3], ad);
            }
            uint32_t bh[8][2], bl[8][2];
#pragma unroll
            for (int jp = 0; jp < 4; jp++) {
                uint32_t ad = smaddr(&sWh[(wn + jp * 16 + b_nrow) * 72 + kc * 16 + b_kcol]);
                ldsm_x4(bh[2 * jp][0], bh[2 * jp][1], bh[2 * jp + 1][0], bh[2 * jp + 1][1], ad);
                ad = smaddr(&sWl[(wn + jp * 16 + b_nrow) * 72 + kc * 16 + b_kcol]);
                ldsm_x4(bl[2 * jp][0], bl[2 * jp][1], bl[2 * jp + 1][0], bl[2 * jp + 1][1], ad);
            }
#pragma unroll
            for (int i = 0; i < 2; i++)
#pragma unroll
                for (int j = 0; j < 8; j++) {
                    mma_bf16(acc[i][j], ah[i], bh[j]);
                    mma_bf16(acc[i][j], ah[i], bl[j]);
                    mma_bf16(acc[i][j], al[i], bh[j]);
                }
        }
        __syncthreads();
    }

    const int g = lane >> 2, t = lane & 3;
    if (MODE == 0) {
#pragma unroll
        for (int i = 0; i < 2; i++)
#pragma unroll
            for (int j = 0; j < 8; j++)
#pragma unroll
                for (int e = 0; e < 4; e++) {
                    int row = m0 + wm + i * 16 + g + (e >> 1) * 8;
                    int col = n0 + wn + j * 8 + 2 * t + (e & 1);
                    float val = acc[i][j][e] + bias[col];
                    int h = col / 192;
                    int rem = col - h * 192;
                    int d = rem / 3;
                    int which = rem - d * 3;
                    int bb = row >> 11;
                    int nn = row & (NSEQ - 1);
                    size_t idx = ((size_t)(bb * NH + h) * NSEQ + nn) * HD + d;
                    bf16 hi, lo;
                    if (which == 0) {
                        bsplit(val * 0.125f, hi, lo);
                        g_qh[idx] = hi; g_ql[idx] = lo;
                    } else if (which == 1) {
                        bsplit(val, hi, lo);
                        g_kh[idx] = hi; g_kl[idx] = lo;
                    } else {
                        bsplit(val, hi, lo);
                        g_vh[idx] = hi; g_vl[idx] = lo;
                    }
                }
    } else {
#pragma unroll
        for (int i = 0; i < 2; i++)
#pragma unroll
            for (int j = 0; j < 8; j++)
#pragma unroll
                for (int e = 0; e < 4; e++) {
                    int row = m0 + wm + i * 16 + g + (e >> 1) * 8;
                    int col = n0 + wn + j * 8 + 2 * t + (e & 1);
                    Cout[(size_t)row * EMB + col] = acc[i][j][e] + bias[col];
                }
    }
}

// ---------------- flash attention (register softmax, cp.async KV pipeline) ---
// Block = 128 q-rows of one (b,h). KV tiles of 128. 8 warps x 16 q-rows each.
// smem: Q hi/lo (2 tiles) + double-buffered {Kh,Kl,Vh,Vl} (8 tiles), 72-stride.
#define AT_TILE (128 * 72)
#define ATTN_SMEM ((2 + 8) * AT_TILE * 2)   // 184320 bytes

__global__ void __launch_bounds__(256) attn_bf16()
{
    extern __shared__ bf16 sm[];
    bf16* Qh = sm;
    bf16* Ql = sm + AT_TILE;
    // stage st (0/1), arr (0=Kh,1=Kl,2=Vh,3=Vl)
    auto buf = [&](int st, int arr) -> bf16* { return sm + (2 + st * 4 + arr) * AT_TILE; };

    const int tid  = threadIdx.x;
    const int lane = tid & 31;
    const int warp = tid >> 5;
    const int bh = blockIdx.y;
    const int b  = bh >> 4;
    const int h  = bh & 15;
    const int q0 = blockIdx.x * 128;

    const bf16* Qgh = g_qh + (size_t)bh * NSEQ * HD;
    const bf16* Qgl = g_ql + (size_t)bh * NSEQ * HD;
    const bf16* Kgh = g_kh + (size_t)bh * NSEQ * HD;
    const bf16* Kgl = g_kl + (size_t)bh * NSEQ * HD;
    const bf16* Vgh = g_vh + (size_t)bh * NSEQ * HD;
    const bf16* Vgl = g_vl + (size_t)bh * NSEQ * HD;

    const int a_row = lane & 15;
    const int a_csel = (lane >> 4) * 8;
    const int b_nrow = (lane & 7) + (lane >> 4) * 8;
    const int b_kcol = ((lane >> 3) & 1) * 8;
    const int g = lane >> 2, t = lane & 3;

    auto load_kv = [&](int st, int t0) {
#pragma unroll
        for (int i = 0; i < 4; i++) {
            int s = tid + i * 256;
            int r = s >> 3;
            int c = (s & 7) * 8;
            cp16(buf(st, 0) + r * 72 + c, Kgh + (size_t)(t0 + r) * HD + c);
            cp16(buf(st, 1) + r * 72 + c, Kgl + (size_t)(t0 + r) * HD + c);
            cp16(buf(st, 2) + r * 72 + c, Vgh + (size_t)(t0 + r) * HD + c);
            cp16(buf(st, 3) + r * 72 + c, Vgl + (size_t)(t0 + r) * HD + c);
        }
    };

    // prologue: Q + KV stage 0
#pragma unroll
    for (int i = 0; i < 4; i++) {
        int s = tid + i * 256;
        int r = s >> 3;
        int c = (s & 7) * 8;
        cp16(Qh + r * 72 + c, Qgh + (size_t)(q0 + r) * HD + c);
        cp16(Ql + r * 72 + c, Qgl + (size_t)(q0 + r) * HD + c);
    }
    load_kv(0, 0);
    cpcommit();
    cpwait<0>();
    __syncthreads();

    // Q fragments (hi/lo) into registers, held for whole loop
    uint32_t qh[4][4], ql[4][4];
#pragma unroll
    for (int kc = 0; kc < 4; kc++) {
        uint32_t ad = smaddr(&Qh[(16 * warp + a_row) * 72 + kc * 16 + a_csel]);
        ldsm_x4(qh[kc][0], qh[kc][1], qh[kc][2], qh[kc][3], ad);
        ad = smaddr(&Ql[(16 * warp + a_row) * 72 + kc * 16 + a_csel]);
        ldsm_x4(ql[kc][0], ql[kc][1], ql[kc][2], ql[kc][3], ad);
    }

    float oacc[8][4];
#pragma unroll
    for (int j = 0; j < 8; j++)
#pragma unroll
        for (int e = 0; e < 4; e++) oacc[j][e] = 0.f;
    float m0r = -1e30f, m1r = -1e30f, l0 = 0.f, l1 = 0.f;

    for (int ti = 0; ti < NSEQ / 128; ti++) {
        int cb = ti & 1;
        if (ti + 1 < NSEQ / 128) {
            load_kv(cb ^ 1, (ti + 1) * 128);
            cpcommit();
            cpwait<1>();
        } else {
            cpwait<0>();
        }
        __syncthreads();

        // ---- S = Q K^T (3-pass split) ----
        float sacc[16][4];
#pragma unroll
        for (int j = 0; j < 16; j++)
#pragma unroll
            for (int e = 0; e < 4; e++) sacc[j][e] = 0.f;

        bf16* Kh = buf(cb, 0);
        bf16* Kl = buf(cb, 1);
#pragma unroll
        for (int kc = 0; kc < 4; kc++) {
#pragma unroll
            for (int jp = 0; jp < 8; jp++) {
                uint32_t bh4[4], bl4[4];
                uint32_t ad = smaddr(&Kh[(jp * 16 + b_nrow) * 72 + kc * 16 + b_kcol]);
                ldsm_x4(bh4[0], bh4[1], bh4[2], bh4[3], ad);
                ad = smaddr(&Kl[(jp * 16 + b_nrow) * 72 + kc * 16 + b_kcol]);
                ldsm_x4(bl4[0], bl4[1], bl4[2], bl4[3], ad);
                mma_bf16(sacc[2 * jp],     qh[kc], &bh4[0]);
                mma_bf16(sacc[2 * jp],     qh[kc], &bl4[0]);
                mma_bf16(sacc[2 * jp],     ql[kc], &bh4[0]);
                mma_bf16(sacc[2 * jp + 1], qh[kc], &bh4[2]);
                mma_bf16(sacc[2 * jp + 1], qh[kc], &bl4[2]);
                mma_bf16(sacc[2 * jp + 1], ql[kc], &bh4[2]);
            }
        }

        // ---- register softmax: rows (16w+g) and (16w+g+8), quad-reduce ----
        float mx0 = -1e30f, mx1 = -1e30f;
#pragma unroll
        for (int j = 0; j < 16; j++) {
            mx0 = fmaxf(mx0, fmaxf(sacc[j][0], sacc[j][1]));
            mx1 = fmaxf(mx1, fmaxf(sacc[j][2], sacc[j][3]));
        }
        mx0 = fmaxf(mx0, __shfl_xor_sync(0xffffffffu, mx0, 1));
        mx0 = fmaxf(mx0, __shfl_xor_sync(0xffffffffu, mx0, 2));
        mx1 = fmaxf(mx1, __shfl_xor_sync(0xffffffffu, mx1, 1));
        mx1 = fmaxf(mx1, __shfl_xor_sync(0xffffffffu, mx1, 2));
        float mn0 = fmaxf(m0r, mx0), mn1 = fmaxf(m1r, mx1);
        float al0 = fast_exp(m0r - mn0), al1 = fast_exp(m1r - mn1);
        m0r = mn0; m1r = mn1;

        float s0 = 0.f, s1 = 0.f;
        uint32_t aph[8][4], apl[8][4];
#pragma unroll
        for (int j2 = 0; j2 < 8; j2++) {
            float p[8];
            p[0] = fast_exp(sacc[2 * j2][0] - mn0);
            p[1] = fast_exp(sacc[2 * j2][1] - mn0);
            p[2] = fast_exp(sacc[2 * j2][2] - mn1);
            p[3] = fast_exp(sacc[2 * j2][3] - mn1);
            p[4] = fast_exp(sacc[2 * j2 + 1][0] - mn0);
            p[5] = fast_exp(sacc[2 * j2 + 1][1] - mn0);
            p[6] = fast_exp(sacc[2 * j2 + 1][2] - mn1);
            p[7] = fast_exp(sacc[2 * j2 + 1][3] - mn1);
            s0 += p[0] + p[1] + p[4] + p[5];
            s1 += p[2] + p[3] + p[6] + p[7];
            bf16 hb[8]; float lf[8];
#pragma unroll
            for (int e = 0; e < 8; e++) {
                hb[e] = __float2bfloat16(p[e]);
                lf[e] = p[e] - __bfloat162float(hb[e]);
            }
            aph[j2][0] = pack2(hb[0], hb[1]);
            aph[j2][1] = pack2(hb[2], hb[3]);
            aph[j2][2] = pack2(hb[4], hb[5]);
            aph[j2][3] = pack2(hb[6], hb[7]);
            apl[j2][0] = pack2(__float2bfloat16(lf[0]), __float2bfloat16(lf[1]));
            apl[j2][1] = pack2(__float2bfloat16(lf[2]), __float2bfloat16(lf[3]));
            apl[j2][2] = pack2(__float2bfloat16(lf[4]), __float2bfloat16(lf[5]));
            apl[j2][3] = pack2(__float2bfloat16(lf[6]), __float2bfloat16(lf[7]));
        }
        s0 += __shfl_xor_sync(0xffffffffu, s0, 1);
        s0 += __shfl_xor_sync(0xffffffffu, s0, 2);
        s1 += __shfl_xor_sync(0xffffffffu, s1, 1);
        s1 += __shfl_xor_sync(0xffffffffu, s1, 2);
        l0 = l0 * al0 + s0;
        l1 = l1 * al1 + s1;

#pragma unroll
        for (int j = 0; j < 8; j++) {
            oacc[j][0] *= al0; oacc[j][1] *= al0;
            oacc[j][2] *= al1; oacc[j][3] *= al1;
        }

        // ---- O += P V (3-pass split; V via trans ldmatrix) ----
        bf16* Vh = buf(cb, 2);
        bf16* Vl = buf(cb, 3);
#pragma unroll
        for (int kc = 0; kc < 8; kc++) {
#pragma unroll
            for (int jp = 0; jp < 4; jp++) {
                uint32_t bh4[4], bl4[4];
                uint32_t ad = smaddr(&Vh[(kc * 16 + a_row) * 72 + jp * 16 + a_csel]);
                ldsm_x4t(bh4[0], bh4[1], bh4[2], bh4[3], ad);
                ad = smaddr(&Vl[(kc * 16 + a_row) * 72 + jp * 16 + a_csel]);
                ldsm_x4t(bl4[0], bl4[1], bl4[2], bl4[3], ad);
                mma_bf16(oacc[2 * jp],     aph[kc], &bh4[0]);
                mma_bf16(oacc[2 * jp],     aph[kc], &bl4[0]);
                mma_bf16(oacc[2 * jp],     apl[kc], &bh4[0]);
                mma_bf16(oacc[2 * jp + 1], aph[kc], &bh4[2]);
                mma_bf16(oacc[2 * jp + 1], aph[kc], &bl4[2]);
                mma_bf16(oacc[2 * jp + 1], apl[kc], &bh4[2]);
            }
        }
        __syncthreads();
    }

    // ---- epilogue: split(O/l) -> g_atth/g_attl at [b, q, h*64+d] ----
    float inv0 = 1.0f / l0;
    float inv1 = 1.0f / l1;
#pragma unroll
    for (int j = 0; j < 8; j++)
#pragma unroll
        for (int e = 0; e < 4; e++) {
            int row = 16 * warp + g + (e >> 1) * 8;
            int col = j * 8 + 2 * t + (e & 1);
            float val = oacc[j][e] * ((e >> 1) ? inv1 : inv0);
            size_t off = ((size_t)b * NSEQ + q0 + row) * EMB + h * HD + col;
            bf16 hi, lo;
            bsplit(val, hi, lo);
            g_atth[off] = hi;
            g_attl[off] = lo;
        }
}

// ---------------------------------------------------------------------------
extern "C" void kernel_launch(void* const* d_in, const int* in_sizes, int n_in,
                              void* d_out, int out_size)
{
    const float* x      = (const float*)d_in[0];
    const float* w_qkv  = (const float*)d_in[1];
    const float* b_qkv  = (const float*)d_in[2];
    const float* w_proj = (const float*)d_in[3];
    const float* b_proj = (const float*)d_in[4];
    float* out = (float*)d_out;

    cudaFuncSetAttribute(gemm_bf16<0>, cudaFuncAttributeMaxDynamicSharedMemorySize, GEMM_SMEM);
    cudaFuncSetAttribute(gemm_bf16<1>, cudaFuncAttributeMaxDynamicSharedMemorySize, GEMM_SMEM);
    cudaFuncSetAttribute(attn_bf16, cudaFuncAttributeMaxDynamicSharedMemorySize, (int)ATTN_SMEM);

    bf16 *xh, *xl, *wqh, *wql, *wph, *wpl, *atth, *attl;
    cudaGetSymbolAddress((void**)&xh,  g_xh);  cudaGetSymbolAddress((void**)&xl,  g_xl);
    cudaGetSymbolAddress((void**)&wqh, g_wqh); cudaGetSymbolAddress((void**)&wql, g_wql);
    cudaGetSymbolAddress((void**)&wph, g_wph); cudaGetSymbolAddress((void**)&wpl, g_wpl);
    cudaGetSymbolAddress((void**)&atth, g_atth); cudaGetSymbolAddress((void**)&attl, g_attl);

    // 1) split inputs to bf16 hi/lo
    split_kernel<<<(NTOK * EMB) / 1024, 256>>>((const float4*)x,
        (__nv_bfloat162*)xh, (__nv_bfloat162*)xl, NTOK * EMB / 4);
    split_kernel<<<(QKVN * EMB) / 1024, 256>>>((const float4*)w_qkv,
        (__nv_bfloat162*)wqh, (__nv_bfloat162*)wql, QKVN * EMB / 4);
    split_kernel<<<(EMB * EMB) / 1024, 256>>>((const float4*)w_proj,
        (__nv_bfloat162*)wph, (__nv_bfloat162*)wpl, EMB * EMB / 4);

    // 2) QKV projection + scatter (q pre-scaled by 1/8, split to bf16 hi/lo)
    gemm_bf16<0><<<dim3(QKVN / 128, NTOK / 128), 256, GEMM_SMEM>>>(
        xh, xl, wqh, wql, b_qkv, nullptr);

    // 3) flash attention
    attn_bf16<<<dim3(NSEQ / 128, BB * NH), 256, ATTN_SMEM>>>();

    // 4) output projection
    gemm_bf16<1><<<dim3(EMB / 128, NTOK / 128), 256, GEMM_SMEM>>>(
        atth, attl, wph, wpl, b_proj, out);
}

// round 5
// speedup vs baseline: 3.5112x; 1.1305x over previous
#include <cuda_runtime.h>
#include <cuda_bf16.h>
#include <math.h>
#include <stdint.h>

#define BB   4
#define NSEQ 2048
#define EMB  1024
#define NH   16
#define HD   64
#define NTOK (BB * NSEQ)      // 8192
#define QKVN (3 * EMB)        // 3072

typedef __nv_bfloat16 bf16;

// ---------------- scratch (__device__ globals; allocation-free) -------------
__device__ bf16 g_xh[NTOK * EMB],  g_xl[NTOK * EMB];
__device__ bf16 g_wqh[QKVN * EMB], g_wql[QKVN * EMB];
__device__ bf16 g_wph[EMB * EMB],  g_wpl[EMB * EMB];
__device__ bf16 g_qh[BB*NH*NSEQ*HD], g_ql[BB*NH*NSEQ*HD];
__device__ bf16 g_kh[BB*NH*NSEQ*HD], g_kl[BB*NH*NSEQ*HD];
__device__ bf16 g_vh[BB*NH*NSEQ*HD], g_vl[BB*NH*NSEQ*HD];
__device__ bf16 g_atth[NTOK * EMB], g_attl[NTOK * EMB];

// ---------------- helpers ----------------------------------------------------
__device__ __forceinline__ uint32_t smaddr(const void* p) {
    return (uint32_t)__cvta_generic_to_shared(p);
}
__device__ __forceinline__ void ldsm_x4(uint32_t& r0, uint32_t& r1, uint32_t& r2,
                                        uint32_t& r3, uint32_t a) {
    asm volatile("ldmatrix.sync.aligned.m8n8.x4.shared.b16 {%0,%1,%2,%3},[%4];\n"
                 : "=r"(r0), "=r"(r1), "=r"(r2), "=r"(r3) : "r"(a));
}
__device__ __forceinline__ void ldsm_x4t(uint32_t& r0, uint32_t& r1, uint32_t& r2,
                                         uint32_t& r3, uint32_t a) {
    asm volatile("ldmatrix.sync.aligned.m8n8.x4.trans.shared.b16 {%0,%1,%2,%3},[%4];\n"
                 : "=r"(r0), "=r"(r1), "=r"(r2), "=r"(r3) : "r"(a));
}
__device__ __forceinline__ void mma_bf16(float c[4], const uint32_t a[4],
                                         const uint32_t b[2]) {
    asm volatile(
        "mma.sync.aligned.m16n8k16.row.col.f32.bf16.bf16.f32 "
        "{%0,%1,%2,%3}, {%4,%5,%6,%7}, {%8,%9}, {%0,%1,%2,%3};\n"
        : "+f"(c[0]), "+f"(c[1]), "+f"(c[2]), "+f"(c[3])
        : "r"(a[0]), "r"(a[1]), "r"(a[2]), "r"(a[3]), "r"(b[0]), "r"(b[1]));
}
__device__ __forceinline__ void bsplit(float v, bf16& h, bf16& l) {
    h = __float2bfloat16(v);
    l = __float2bfloat16(v - __bfloat162float(h));
}
__device__ __forceinline__ uint32_t pack2(bf16 a, bf16 b) {
    __nv_bfloat162 t; t.x = a; t.y = b;
    return *(uint32_t*)&t;
}
// FMA-pipe exp (no MUFU). Valid for x <= 0 (clamped below).
__device__ __forceinline__ float fast_exp(float x) {
    x = fmaxf(x, -86.0f);
    float y = x * 1.4426950408889634f;
    float r = rintf(y);
    float f = y - r;
    float p = 0.00133819f;
    p = fmaf(p, f, 0.00961804f);
    p = fmaf(p, f, 0.05550411f);
    p = fmaf(p, f, 0.24022651f);
    p = fmaf(p, f, 0.69314718f);
    p = fmaf(p, f, 1.0f);
    int e = (int)r;
    return p * __int_as_float((e + 127) << 23);
}
__device__ __forceinline__ void cp16(void* dst, const void* src) {
    asm volatile("cp.async.cg.shared.global [%0],[%1],16;\n"
                 :: "r"(smaddr(dst)), "l"(src));
}
__device__ __forceinline__ void cpcommit() {
    asm volatile("cp.async.commit_group;\n");
}
template <int N>
__device__ __forceinline__ void cpwait() {
    asm volatile("cp.async.wait_group %0;\n" :: "n"(N));
}
// SW64-style XOR swizzle for 64-byte rows (16B granularity), conflict-free
// for both ldmatrix row reads and cp.async 16B stores.
__device__ __forceinline__ uint32_t sw64(uint32_t off) {
    return off ^ ((off >> 3) & 0x30);
}

// ---------------- split kernel (fp32 -> bf16 hi/lo) --------------------------
__global__ void __launch_bounds__(256) split_kernel(
    const float4* __restrict__ in, __nv_bfloat162* __restrict__ h,
    __nv_bfloat162* __restrict__ l, int n4)
{
    int i = blockIdx.x * 256 + threadIdx.x;
    if (i >= n4) return;
    float4 v = in[i];
    bf16 h0, l0, h1, l1, h2, l2, h3, l3;
    bsplit(v.x, h0, l0); bsplit(v.y, h1, l1);
    bsplit(v.z, h2, l2); bsplit(v.w, h3, l3);
    __nv_bfloat162 t;
    t.x = h0; t.y = h1; h[2 * i] = t;
    t.x = h2; t.y = h3; h[2 * i + 1] = t;
    t.x = l0; t.y = l1; l[2 * i] = t;
    t.x = l2; t.y = l3; l[2 * i + 1] = t;
}

// ---------------- GEMM (NT, bf16 3-pass split, mma.sync) ---------------------
// 128x128 tile, K-chunks of 32, 3-stage cp.async, 2 CTAs/SM (96 KB smem).
// Layout: 64-byte rows (32 bf16), XOR-swizzled, no padding.
#define KCH      32
#define NKT      (EMB / KCH)          // 32
#define GT_B     (128 * 64)           // 8 KB per array per stage
#define G_STAGES 3
#define GEMM_SMEM (G_STAGES * 4 * GT_B)  // 98304

template <int MODE>
__global__ void __launch_bounds__(256, 2) gemm_bf16(
    const bf16* __restrict__ Ah_, const bf16* __restrict__ Al_,
    const bf16* __restrict__ Wh_, const bf16* __restrict__ Wl_,
    const float* __restrict__ bias, float* __restrict__ Cout)
{
    constexpr int K = EMB;
    extern __shared__ char smg[];

    const int tid  = threadIdx.x;
    const int lane = tid & 31;
    const int warp = tid >> 5;
    const int m0 = blockIdx.y * 128;
    const int n0 = blockIdx.x * 128;
    const int wm = (warp >> 1) * 32;
    const int wn = (warp & 1) * 64;

    const int a_row = lane & 15;
    const int a_csel = (lane >> 4) * 8;
    const int b_nrow = (lane & 7) + (lane >> 4) * 8;
    const int b_kcol = ((lane >> 3) & 1) * 8;

    float acc[2][8][4];
#pragma unroll
    for (int i = 0; i < 2; i++)
#pragma unroll
        for (int j = 0; j < 8; j++)
#pragma unroll
            for (int e = 0; e < 4; e++) acc[i][j][e] = 0.f;

    auto tile = [&](int st, int arr) -> char* { return smg + (st * 4 + arr) * GT_B; };

    auto load_chunk = [&](int st, int kt) {
        const int k0 = kt * KCH;
#pragma unroll
        for (int arr = 0; arr < 4; arr++) {
            const bf16* base =
                (arr == 0) ? Ah_ + (size_t)m0 * K :
                (arr == 1) ? Al_ + (size_t)m0 * K :
                (arr == 2) ? Wh_ + (size_t)n0 * K : Wl_ + (size_t)n0 * K;
            char* dst = tile(st, arr);
#pragma unroll
            for (int i = 0; i < 2; i++) {
                int idx = tid + i * 256;
                int r  = idx >> 2;
                int c4 = idx & 3;
                uint32_t off = sw64((uint32_t)(r * 64 + c4 * 16));
                cp16(dst + off, base + (size_t)r * K + k0 + c4 * 8);
            }
        }
    };

    load_chunk(0, 0); cpcommit();
    load_chunk(1, 1); cpcommit();

    for (int kt = 0; kt < NKT; kt++) {
        const int st = kt % 3;
        if (kt == NKT - 1) cpwait<0>(); else cpwait<1>();
        __syncthreads();

        char* sAh = tile(st, 0);
        char* sAl = tile(st, 1);
        char* sWh = tile(st, 2);
        char* sWl = tile(st, 3);
#pragma unroll
        for (int kc = 0; kc < 2; kc++) {
            const uint32_t acol = (uint32_t)((kc * 16 + a_csel) * 2);
            const uint32_t bcol = (uint32_t)((kc * 16 + b_kcol) * 2);
            uint32_t ah[2][4], al[2][4];
#pragma unroll
            for (int i = 0; i < 2; i++) {
                uint32_t off = sw64((uint32_t)((wm + i * 16 + a_row) * 64) + acol);
                ldsm_x4(ah[i][0], ah[i][1], ah[i][2], ah[i][3], smaddr(sAh + off));
                ldsm_x4(al[i][0], al[i][1], al[i][2], al[i][3], smaddr(sAl + off));
            }
            uint32_t bh[8][2], bl[8][2];
#pragma unroll
            for (int jp = 0; jp < 4; jp++) {
                uint32_t off = sw64((uint32_t)((wn + jp * 16 + b_nrow) * 64) + bcol);
                ldsm_x4(bh[2 * jp][0], bh[2 * jp][1], bh[2 * jp + 1][0], bh[2 * jp + 1][1],
                        smaddr(sWh + off));
                ldsm_x4(bl[2 * jp][0], bl[2 * jp][1], bl[2 * jp + 1][0], bl[2 * jp + 1][1],
                        smaddr(sWl + off));
            }
#pragma unroll
            for (int i = 0; i < 2; i++)
#pragma unroll
                for (int j = 0; j < 8; j++) {
                    mma_bf16(acc[i][j], ah[i], bh[j]);
                    mma_bf16(acc[i][j], ah[i], bl[j]);
                    mma_bf16(acc[i][j], al[i], bh[j]);
                }
        }

        if (kt + 2 < NKT) {
            load_chunk((kt + 2) % 3, kt + 2);
            cpcommit();
        }
    }

    const int g = lane >> 2, t = lane & 3;
    if (MODE == 0) {
#pragma unroll
        for (int i = 0; i < 2; i++)
#pragma unroll
            for (int j = 0; j < 8; j++)
#pragma unroll
                for (int e = 0; e < 4; e++) {
                    int row = m0 + wm + i * 16 + g + (e >> 1) * 8;
                    int col = n0 + wn + j * 8 + 2 * t + (e & 1);
                    float val = acc[i][j][e] + bias[col];
                    int h = col / 192;
                    int rem = col - h * 192;
                    int d = rem / 3;
                    int which = rem - d * 3;
                    int bb = row >> 11;
                    int nn = row & (NSEQ - 1);
                    size_t idx = ((size_t)(bb * NH + h) * NSEQ + nn) * HD + d;
                    bf16 hi, lo;
                    if (which == 0) {
                        bsplit(val * 0.125f, hi, lo);
                        g_qh[idx] = hi; g_ql[idx] = lo;
                    } else if (which == 1) {
                        bsplit(val, hi, lo);
                        g_kh[idx] = hi; g_kl[idx] = lo;
                    } else {
                        bsplit(val, hi, lo);
                        g_vh[idx] = hi; g_vl[idx] = lo;
                    }
                }
    } else {
#pragma unroll
        for (int i = 0; i < 2; i++)
#pragma unroll
            for (int j = 0; j < 8; j++)
#pragma unroll
                for (int e = 0; e < 4; e++) {
                    int row = m0 + wm + i * 16 + g + (e >> 1) * 8;
                    int col = n0 + wn + j * 8 + 2 * t + (e & 1);
                    Cout[(size_t)row * EMB + col] = acc[i][j][e] + bias[col];
                }
    }
}

// ---------------- flash attention (register softmax, cp.async KV pipeline) ---
#define AT_TILE (128 * 72)
#define ATTN_SMEM ((2 + 8) * AT_TILE * 2)   // 184320 bytes

__global__ void __launch_bounds__(256) attn_bf16()
{
    extern __shared__ bf16 sm[];
    bf16* Qh = sm;
    bf16* Ql = sm + AT_TILE;
    auto buf = [&](int st, int arr) -> bf16* { return sm + (2 + st * 4 + arr) * AT_TILE; };

    const int tid  = threadIdx.x;
    const int lane = tid & 31;
    const int warp = tid >> 5;
    const int bh = blockIdx.y;
    const int b  = bh >> 4;
    const int h  = bh & 15;
    const int q0 = blockIdx.x * 128;

    const bf16* Qgh = g_qh + (size_t)bh * NSEQ * HD;
    const bf16* Qgl = g_ql + (size_t)bh * NSEQ * HD;
    const bf16* Kgh = g_kh + (size_t)bh * NSEQ * HD;
    const bf16* Kgl = g_kl + (size_t)bh * NSEQ * HD;
    const bf16* Vgh = g_vh + (size_t)bh * NSEQ * HD;
    const bf16* Vgl = g_vl + (size_t)bh * NSEQ * HD;

    const int a_row = lane & 15;
    const int a_csel = (lane >> 4) * 8;
    const int b_nrow = (lane & 7) + (lane >> 4) * 8;
    const int b_kcol = ((lane >> 3) & 1) * 8;
    const int g = lane >> 2, t = lane & 3;

    auto load_kv = [&](int st, int t0) {
#pragma unroll
        for (int i = 0; i < 4; i++) {
            int s = tid + i * 256;
            int r = s >> 3;
            int c = (s & 7) * 8;
            cp16(buf(st, 0) + r * 72 + c, Kgh + (size_t)(t0 + r) * HD + c);
            cp16(buf(st, 1) + r * 72 + c, Kgl + (size_t)(t0 + r) * HD + c);
            cp16(buf(st, 2) + r * 72 + c, Vgh + (size_t)(t0 + r) * HD + c);
            cp16(buf(st, 3) + r * 72 + c, Vgl + (size_t)(t0 + r) * HD + c);
        }
    };

#pragma unroll
    for (int i = 0; i < 4; i++) {
        int s = tid + i * 256;
        int r = s >> 3;
        int c = (s & 7) * 8;
        cp16(Qh + r * 72 + c, Qgh + (size_t)(q0 + r) * HD + c);
        cp16(Ql + r * 72 + c, Qgl + (size_t)(q0 + r) * HD + c);
    }
    load_kv(0, 0);
    cpcommit();
    cpwait<0>();
    __syncthreads();

    uint32_t qh[4][4], ql[4][4];
#pragma unroll
    for (int kc = 0; kc < 4; kc++) {
        uint32_t ad = smaddr(&Qh[(16 * warp + a_row) * 72 + kc * 16 + a_csel]);
        ldsm_x4(qh[kc][0], qh[kc][1], qh[kc][2], qh[kc][3], ad);
        ad = smaddr(&Ql[(16 * warp + a_row) * 72 + kc * 16 + a_csel]);
        ldsm_x4(ql[kc][0], ql[kc][1], ql[kc][2], ql[kc][3], ad);
    }

    float oacc[8][4];
#pragma unroll
    for (int j = 0; j < 8; j++)
#pragma unroll
        for (int e = 0; e < 4; e++) oacc[j][e] = 0.f;
    float m0r = -1e30f, m1r = -1e30f, l0 = 0.f, l1 = 0.f;

    for (int ti = 0; ti < NSEQ / 128; ti++) {
        int cb = ti & 1;
        if (ti + 1 < NSEQ / 128) {
            load_kv(cb ^ 1, (ti + 1) * 128);
            cpcommit();
            cpwait<1>();
        } else {
            cpwait<0>();
        }
        __syncthreads();

        float sacc[16][4];
#pragma unroll
        for (int j = 0; j < 16; j++)
#pragma unroll
            for (int e = 0; e < 4; e++) sacc[j][e] = 0.f;

        bf16* Kh = buf(cb, 0);
        bf16* Kl = buf(cb, 1);
#pragma unroll
        for (int kc = 0; kc < 4; kc++) {
#pragma unroll
            for (int jp = 0; jp < 8; jp++) {
                uint32_t bh4[4], bl4[4];
                uint32_t ad = smaddr(&Kh[(jp * 16 + b_nrow) * 72 + kc * 16 + b_kcol]);
                ldsm_x4(bh4[0], bh4[1], bh4[2], bh4[3], ad);
                ad = smaddr(&Kl[(jp * 16 + b_nrow) * 72 + kc * 16 + b_kcol]);
                ldsm_x4(bl4[0], bl4[1], bl4[2], bl4[3], ad);
                mma_bf16(sacc[2 * jp],     qh[kc], &bh4[0]);
                mma_bf16(sacc[2 * jp],     qh[kc], &bl4[0]);
                mma_bf16(sacc[2 * jp],     ql[kc], &bh4[0]);
                mma_bf16(sacc[2 * jp + 1], qh[kc], &bh4[2]);
                mma_bf16(sacc[2 * jp + 1], qh[kc], &bl4[2]);
                mma_bf16(sacc[2 * jp + 1], ql[kc], &bh4[2]);
            }
        }

        float mx0 = -1e30f, mx1 = -1e30f;
#pragma unroll
        for (int j = 0; j < 16; j++) {
            mx0 = fmaxf(mx0, fmaxf(sacc[j][0], sacc[j][1]));
            mx1 = fmaxf(mx1, fmaxf(sacc[j][2], sacc[j][3]));
        }
        mx0 = fmaxf(mx0, __shfl_xor_sync(0xffffffffu, mx0, 1));
        mx0 = fmaxf(mx0, __shfl_xor_sync(0xffffffffu, mx0, 2));
        mx1 = fmaxf(mx1, __shfl_xor_sync(0xffffffffu, mx1, 1));
        mx1 = fmaxf(mx1, __shfl_xor_sync(0xffffffffu, mx1, 2));
        float mn0 = fmaxf(m0r, mx0), mn1 = fmaxf(m1r, mx1);
        float al0 = fast_exp(m0r - mn0), al1 = fast_exp(m1r - mn1);
        m0r = mn0; m1r = mn1;

        float s0 = 0.f, s1 = 0.f;
        uint32_t aph[8][4], apl[8][4];
#pragma unroll
        for (int j2 = 0; j2 < 8; j2++) {
            float p[8];
            p[0] = fast_exp(sacc[2 * j2][0] - mn0);
            p[1] = fast_exp(sacc[2 * j2][1] - mn0);
            p[2] = fast_exp(sacc[2 * j2][2] - mn1);
            p[3] = fast_exp(sacc[2 * j2][3] - mn1);
            p[4] = fast_exp(sacc[2 * j2 + 1][0] - mn0);
            p[5] = fast_exp(sacc[2 * j2 + 1][1] - mn0);
            p[6] = fast_exp(sacc[2 * j2 + 1][2] - mn1);
            p[7] = fast_exp(sacc[2 * j2 + 1][3] - mn1);
            s0 += p[0] + p[1] + p[4] + p[5];
            s1 += p[2] + p[3] + p[6] + p[7];
            bf16 hb[8]; float lf[8];
#pragma unroll
            for (int e = 0; e < 8; e++) {
                hb[e] = __float2bfloat16(p[e]);
                lf[e] = p[e] - __bfloat162float(hb[e]);
            }
            aph[j2][0] = pack2(hb[0], hb[1]);
            aph[j2][1] = pack2(hb[2], hb[3]);
            aph[j2][2] = pack2(hb[4], hb[5]);
            aph[j2][3] = pack2(hb[6], hb[7]);
            apl[j2][0] = pack2(__float2bfloat16(lf[0]), __float2bfloat16(lf[1]));
            apl[j2][1] = pack2(__float2bfloat16(lf[2]), __float2bfloat16(lf[3]));
            apl[j2][2] = pack2(__float2bfloat16(lf[4]), __float2bfloat16(lf[5]));
            apl[j2][3] = pack2(__float2bfloat16(lf[6]), __float2bfloat16(lf[7]));
        }
        s0 += __shfl_xor_sync(0xffffffffu, s0, 1);
        s0 += __shfl_xor_sync(0xffffffffu, s0, 2);
        s1 += __shfl_xor_sync(0xffffffffu, s1, 1);
        s1 += __shfl_xor_sync(0xffffffffu, s1, 2);
        l0 = l0 * al0 + s0;
        l1 = l1 * al1 + s1;

#pragma unroll
        for (int j = 0; j < 8; j++) {
            oacc[j][0] *= al0; oacc[j][1] *= al0;
            oacc[j][2] *= al1; oacc[j][3] *= al1;
        }

        bf16* Vh = buf(cb, 2);
        bf16* Vl = buf(cb, 3);
#pragma unroll
        for (int kc = 0; kc < 8; kc++) {
#pragma unroll
            for (int jp = 0; jp < 4; jp++) {
                uint32_t bh4[4], bl4[4];
                uint32_t ad = smaddr(&Vh[(kc * 16 + a_row) * 72 + jp * 16 + a_csel]);
                ldsm_x4t(bh4[0], bh4[1], bh4[2], bh4[3], ad);
                ad = smaddr(&Vl[(kc * 16 + a_row) * 72 + jp * 16 + a_csel]);
                ldsm_x4t(bl4[0], bl4[1], bl4[2], bl4[3], ad);
                mma_bf16(oacc[2 * jp],     aph[kc], &bh4[0]);
                mma_bf16(oacc[2 * jp],     aph[kc], &bl4[0]);
                mma_bf16(oacc[2 * jp],     apl[kc], &bh4[0]);
                mma_bf16(oacc[2 * jp + 1], aph[kc], &bh4[2]);
                mma_bf16(oacc[2 * jp + 1], aph[kc], &bl4[2]);
                mma_bf16(oacc[2 * jp + 1], apl[kc], &bh4[2]);
            }
        }
        __syncthreads();
    }

    float inv0 = 1.0f / l0;
    float inv1 = 1.0f / l1;
#pragma unroll
    for (int j = 0; j < 8; j++)
#pragma unroll
        for (int e = 0; e < 4; e++) {
            int row = 16 * warp + g + (e >> 1) * 8;
            int col = j * 8 + 2 * t + (e & 1);
            float val = oacc[j][e] * ((e >> 1) ? inv1 : inv0);
            size_t off = ((size_t)b * NSEQ + q0 + row) * EMB + h * HD + col;
            bf16 hi, lo;
            bsplit(val, hi, lo);
            g_atth[off] = hi;
            g_attl[off] = lo;
        }
}

// ---------------------------------------------------------------------------
extern "C" void kernel_launch(void* const* d_in, const int* in_sizes, int n_in,
                              void* d_out, int out_size)
{
    const float* x      = (const float*)d_in[0];
    const float* w_qkv  = (const float*)d_in[1];
    const float* b_qkv  = (const float*)d_in[2];
    const float* w_proj = (const float*)d_in[3];
    const float* b_proj = (const float*)d_in[4];
    float* out = (float*)d_out;

    cudaFuncSetAttribute(gemm_bf16<0>, cudaFuncAttributeMaxDynamicSharedMemorySize, GEMM_SMEM);
    cudaFuncSetAttribute(gemm_bf16<1>, cudaFuncAttributeMaxDynamicSharedMemorySize, GEMM_SMEM);
    cudaFuncSetAttribute(attn_bf16, cudaFuncAttributeMaxDynamicSharedMemorySize, (int)ATTN_SMEM);

    bf16 *xh, *xl, *wqh, *wql, *wph, *wpl, *atth, *attl;
    cudaGetSymbolAddress((void**)&xh,  g_xh);  cudaGetSymbolAddress((void**)&xl,  g_xl);
    cudaGetSymbolAddress((void**)&wqh, g_wqh); cudaGetSymbolAddress((void**)&wql, g_wql);
    cudaGetSymbolAddress((void**)&wph, g_wph); cudaGetSymbolAddress((void**)&wpl, g_wpl);
    cudaGetSymbolAddress((void**)&atth, g_atth); cudaGetSymbolAddress((void**)&attl, g_attl);

    // 1) split inputs to bf16 hi/lo
    split_kernel<<<(NTOK * EMB) / 1024, 256>>>((const float4*)x,
        (__nv_bfloat162*)xh, (__nv_bfloat162*)xl, NTOK * EMB / 4);
    split_kernel<<<(QKVN * EMB) / 1024, 256>>>((const float4*)w_qkv,
        (__nv_bfloat162*)wqh, (__nv_bfloat162*)wql, QKVN * EMB / 4);
    split_kernel<<<(EMB * EMB) / 1024, 256>>>((const float4*)w_proj,
        (__nv_bfloat162*)wph, (__nv_bfloat162*)wpl, EMB * EMB / 4);

    // 2) QKV projection + scatter (q pre-scaled by 1/8, split to bf16 hi/lo)
    gemm_bf16<0><<<dim3(QKVN / 128, NTOK / 128), 256, GEMM_SMEM>>>(
        xh, xl, wqh, wql, b_qkv, nullptr);

    // 3) flash attention
    attn_bf16<<<dim3(NSEQ / 128, BB * NH), 256, ATTN_SMEM>>>();

    // 4) output projection
    gemm_bf16<1><<<dim3(EMB / 128, NTOK / 128), 256, GEMM_SMEM>>>(
        atth, attl, wph, wpl, b_proj, out);
}